// round 2
// baseline (speedup 1.0000x reference)
#include <cuda_runtime.h>
#include <cstdint>

// Problem constants
#define D      1024
#define PP     2048
#define BB     2
#define RR     128
#define SS     128
#define KTOP   4
#define EE     8192        // 4 frames * 2048
#define NPAIR  3
#define EPSA   1e-8f
#define NEG_INF -3.402823466e38f

// ---------------- static device scratch (no allocation allowed) ----------------
__device__ float g_X[BB][768][D];            // rows 0..127 ref_t, 128..255 ref_s, 256..767 H (r*4+k)
__device__ float g_Sh[NPAIR][BB][256][D];    // rows 0..127 Sh_t, 128..255 Sh_s
__device__ float g_sim[BB][RR][EE];
__device__ float g_T[NPAIR][BB][768][256];
__device__ float g_en2[BB][EE];
__device__ float g_rtn2[BB][RR];
__device__ float g_rsn2[BB][RR];
__device__ float g_shn2[NPAIR][BB][2][SS];
__device__ float g_Hn2[BB][RR][KTOP];
__device__ float g_RHt[BB][RR][KTOP];
__device__ float g_RHs[BB][RR][KTOP];
__device__ float g_nRHt[BB][RR][KTOP];
__device__ float g_nRHs[BB][RR][KTOP];
__device__ int   g_topk[BB][RR][KTOP];
__device__ float g_partial[NPAIR * BB * RR];

// ---------------- helpers ----------------
__device__ __forceinline__ float4 ld4(const float* p) {
    return *reinterpret_cast<const float4*>(p);
}

__device__ __forceinline__ float block_reduce_sum(float v, float* sb, int n) {
    int tid = threadIdx.x;
    sb[tid] = v;
    __syncthreads();
    for (int s = n >> 1; s > 0; s >>= 1) {
        if (tid < s) sb[tid] += sb[tid + s];
        __syncthreads();
    }
    float r = sb[0];
    __syncthreads();
    return r;
}

// packed f32x2 FMA (sm_100+): 2 fp32 FMAs per fma-pipe issue
__device__ __forceinline__ unsigned long long dup2(float a) {
    unsigned long long r;
    asm("mov.b64 %0, {%1, %1};" : "=l"(r) : "f"(a));
    return r;
}
__device__ __forceinline__ unsigned long long fma2(unsigned long long a, unsigned long long b,
                                                   unsigned long long c) {
    unsigned long long d;
    asm("fma.rn.f32x2 %0, %1, %2, %3;" : "=l"(d) : "l"(a), "l"(b), "l"(c));
    return d;
}

// ---------------- gather kernels ----------------
// grid (128, B, 2): r, b, which (0=ref_t from teacher frame0, 1=ref_s from student frame0)
__global__ void gather_refs_kernel(const float* __restrict__ teacher,
                                   const float* __restrict__ student,
                                   const int* __restrict__ ref_perm) {
    __shared__ float sb[256];
    int r = blockIdx.x, b = blockIdx.y, w = blockIdx.z;
    int p = ref_perm[r];
    const float* src = (w == 0)
        ? teacher + (((size_t)b * 8 + 0) * PP + p) * D
        : student + (((size_t)b * 4 + 0) * PP + p) * D;
    float* dst = &g_X[b][w * 128 + r][0];
    int tid = threadIdx.x;
    float4 v = ld4(src + tid * 4);
    *reinterpret_cast<float4*>(dst + tid * 4) = v;
    float ss = v.x * v.x + v.y * v.y + v.z * v.z + v.w * v.w;
    ss = block_reduce_sum(ss, sb, 256);
    if (tid == 0) {
        if (w == 0) g_rtn2[b][r] = ss; else g_rsn2[b][r] = ss;
    }
}

// grid (128, B, 6): s, b, z=pair*2+w.  w=0: Sh_t (teacher frame 2*(pair+1)); w=1: Sh_s (student frame pair+1)
__global__ void gather_sh_kernel(const float* __restrict__ teacher,
                                 const float* __restrict__ student,
                                 const int* __restrict__ shared_perm) {
    __shared__ float sb[256];
    int s = blockIdx.x, b = blockIdx.y, z = blockIdx.z;
    int pair = z >> 1, w = z & 1;
    int p = shared_perm[s];
    const float* src = (w == 0)
        ? teacher + (((size_t)b * 8 + 2 * (pair + 1)) * PP + p) * D
        : student + (((size_t)b * 4 + (pair + 1)) * PP + p) * D;
    float* dst = &g_Sh[pair][b][w * 128 + s][0];
    int tid = threadIdx.x;
    float4 v = ld4(src + tid * 4);
    *reinterpret_cast<float4*>(dst + tid * 4) = v;
    float ss = v.x * v.x + v.y * v.y + v.z * v.z + v.w * v.w;
    ss = block_reduce_sum(ss, sb, 256);
    if (tid == 0) g_shn2[pair][b][w][s] = ss;
}

// grid (8192, B): squared norm of every "extra" candidate row
__global__ void extra_norm_kernel(const float* __restrict__ teacher) {
    __shared__ float sb[256];
    int e = blockIdx.x, b = blockIdx.y;
    int f = 1 + 2 * (e >> 11);
    int p = e & 2047;
    const float* src = teacher + (((size_t)b * 8 + f) * PP + p) * D;
    int tid = threadIdx.x;
    float4 v = ld4(src + tid * 4);
    float ss = v.x * v.x + v.y * v.y + v.z * v.z + v.w * v.w;
    ss = block_reduce_sum(ss, sb, 256);
    if (tid == 0) g_en2[b][e] = ss;
}

// ---------------- 128x128x1024 fp32(x2) GEMM core ----------------
// A: 128 rows, row stride 1024 (K-major). B: 128 rows, row stride 1024. C: 128x128 tile, row stride ldc.
// If SCALE, C[m][n] = acc * rsqrt(max(cscale[n],1e-24))
template <bool SCALE>
__device__ __forceinline__ void gemm_core(const float* __restrict__ A,
                                          const float* __restrict__ B,
                                          float* __restrict__ C, int ldc,
                                          const float* __restrict__ cscale) {
    __shared__ __align__(16) float As[16][132];
    __shared__ __align__(16) float Bs[16][132];

    int tid = threadIdx.x;
    int tx = tid & 15;        // 16 col groups
    int ty = tid >> 4;        // 16 row groups
    int r0 = tid >> 2;        // 0..63
    int kq = tid & 3;         // which float4 along k (0..3)
    int r1 = r0 + 64;

    unsigned long long acc[8][4];
#pragma unroll
    for (int i = 0; i < 8; i++)
#pragma unroll
        for (int j = 0; j < 4; j++) acc[i][j] = 0ull;

    const float* Ap0 = A + (size_t)r0 * D + kq * 4;
    const float* Ap1 = A + (size_t)r1 * D + kq * 4;
    const float* Bp0 = B + (size_t)r0 * D + kq * 4;
    const float* Bp1 = B + (size_t)r1 * D + kq * 4;

    float4 ra0 = ld4(Ap0);
    float4 ra1 = ld4(Ap1);
    float4 rb0 = ld4(Bp0);
    float4 rb1 = ld4(Bp1);

    for (int kt = 0; kt < 64; ++kt) {
        int kb = kq * 4;
        As[kb + 0][r0] = ra0.x; As[kb + 1][r0] = ra0.y; As[kb + 2][r0] = ra0.z; As[kb + 3][r0] = ra0.w;
        As[kb + 0][r1] = ra1.x; As[kb + 1][r1] = ra1.y; As[kb + 2][r1] = ra1.z; As[kb + 3][r1] = ra1.w;
        Bs[kb + 0][r0] = rb0.x; Bs[kb + 1][r0] = rb0.y; Bs[kb + 2][r0] = rb0.z; Bs[kb + 3][r0] = rb0.w;
        Bs[kb + 0][r1] = rb1.x; Bs[kb + 1][r1] = rb1.y; Bs[kb + 2][r1] = rb1.z; Bs[kb + 3][r1] = rb1.w;
        __syncthreads();

        if (kt < 63) {
            int ko = (kt + 1) * 16;
            ra0 = ld4(Ap0 + ko);
            ra1 = ld4(Ap1 + ko);
            rb0 = ld4(Bp0 + ko);
            rb1 = ld4(Bp1 + ko);
        }

#pragma unroll
        for (int kk = 0; kk < 16; ++kk) {
            float4 af0 = ld4(&As[kk][ty * 4]);
            float4 af1 = ld4(&As[kk][64 + ty * 4]);
            ulonglong2 bl0 = *reinterpret_cast<const ulonglong2*>(&Bs[kk][tx * 4]);
            ulonglong2 bl1 = *reinterpret_cast<const ulonglong2*>(&Bs[kk][64 + tx * 4]);
            unsigned long long av[8];
            av[0] = dup2(af0.x); av[1] = dup2(af0.y); av[2] = dup2(af0.z); av[3] = dup2(af0.w);
            av[4] = dup2(af1.x); av[5] = dup2(af1.y); av[6] = dup2(af1.z); av[7] = dup2(af1.w);
            unsigned long long bv[4] = {bl0.x, bl0.y, bl1.x, bl1.y};
#pragma unroll
            for (int i = 0; i < 8; i++)
#pragma unroll
                for (int j = 0; j < 4; j++) acc[i][j] = fma2(av[i], bv[j], acc[i][j]);
        }
        __syncthreads();
    }

    // epilogue
    float inv0x = 1.f, inv0y = 1.f, inv0z = 1.f, inv0w = 1.f;
    float inv1x = 1.f, inv1y = 1.f, inv1z = 1.f, inv1w = 1.f;
    if (SCALE) {
        float4 c0 = ld4(cscale + tx * 4);
        float4 c1 = ld4(cscale + 64 + tx * 4);
        inv0x = rsqrtf(fmaxf(c0.x, 1e-24f)); inv0y = rsqrtf(fmaxf(c0.y, 1e-24f));
        inv0z = rsqrtf(fmaxf(c0.z, 1e-24f)); inv0w = rsqrtf(fmaxf(c0.w, 1e-24f));
        inv1x = rsqrtf(fmaxf(c1.x, 1e-24f)); inv1y = rsqrtf(fmaxf(c1.y, 1e-24f));
        inv1z = rsqrtf(fmaxf(c1.z, 1e-24f)); inv1w = rsqrtf(fmaxf(c1.w, 1e-24f));
    }
    union U { unsigned long long u; float2 f; };
#pragma unroll
    for (int ri = 0; ri < 8; ri++) {
        int m = (ri < 4) ? (ty * 4 + ri) : (64 + ty * 4 + (ri - 4));
        float* Cr = C + (size_t)m * ldc;
        U u0, u1, u2, u3;
        u0.u = acc[ri][0]; u1.u = acc[ri][1]; u2.u = acc[ri][2]; u3.u = acc[ri][3];
        float4 o0, o1;
        o0.x = u0.f.x; o0.y = u0.f.y; o0.z = u1.f.x; o0.w = u1.f.y;
        o1.x = u2.f.x; o1.y = u2.f.y; o1.z = u3.f.x; o1.w = u3.f.y;
        if (SCALE) {
            o0.x *= inv0x; o0.y *= inv0y; o0.z *= inv0z; o0.w *= inv0w;
            o1.x *= inv1x; o1.y *= inv1y; o1.z *= inv1z; o1.w *= inv1w;
        }
        *reinterpret_cast<float4*>(Cr + tx * 4) = o0;
        *reinterpret_cast<float4*>(Cr + 64 + tx * 4) = o1;
    }
}

// sim = ref_t . extra^T, column-scaled by rsqrt(|extra|^2). grid (64, B)
__global__ __launch_bounds__(256) void sim_gemm_kernel(const float* __restrict__ teacher) {
    int b = blockIdx.y;
    int n0 = blockIdx.x * 128;
    int fc = n0 >> 11;
    const float* A = &g_X[b][0][0];
    const float* B = teacher + (((size_t)b * 8 + 1 + 2 * fc) * PP + (n0 & 2047)) * D;
    float* C = &g_sim[b][0][n0];
    gemm_core<true>(A, B, C, EE, &g_en2[b][n0]);
}

// T = [ref_t; ref_s; H] . [Sh_t; Sh_s]^T for each (pair, b). grid (2, 6, 6)
__global__ __launch_bounds__(256) void t_gemm_kernel() {
    int z = blockIdx.z;
    int pair = z >> 1, b = z & 1;
    const float* A = &g_X[b][blockIdx.y * 128][0];
    const float* B = &g_Sh[pair][b][blockIdx.x * 128][0];
    float* C = &g_T[pair][b][blockIdx.y * 128][blockIdx.x * 128];
    gemm_core<false>(A, B, C, 256, nullptr);
}

// ---------------- top-k ----------------
// grid (128, B), 256 threads
__global__ void topk_kernel() {
    int r = blockIdx.x, b = blockIdx.y;
    const float* row = &g_sim[b][r][0];
    int tid = threadIdx.x;

    float v0 = NEG_INF, v1 = NEG_INF, v2 = NEG_INF, v3 = NEG_INF;
    int i0 = 0, i1 = 0, i2 = 0, i3 = 0;
    for (int e = tid; e < EE; e += 256) {
        float x = row[e];
        if (x > v3) {
            if (x > v0)      { v3=v2;i3=i2; v2=v1;i2=i1; v1=v0;i1=i0; v0=x;i0=e; }
            else if (x > v1) { v3=v2;i3=i2; v2=v1;i2=i1; v1=x;i1=e; }
            else if (x > v2) { v3=v2;i3=i2; v2=x;i2=e; }
            else             { v3=x;i3=e; }
        }
    }
    __shared__ float sv[1024];
    __shared__ int   si[1024];
    __shared__ float rv[256];
    __shared__ int   ri[256];
    sv[tid*4+0]=v0; si[tid*4+0]=i0;
    sv[tid*4+1]=v1; si[tid*4+1]=i1;
    sv[tid*4+2]=v2; si[tid*4+2]=i2;
    sv[tid*4+3]=v3; si[tid*4+3]=i3;
    __syncthreads();

    for (int sel = 0; sel < KTOP; sel++) {
        float m = NEG_INF;
        int mi = 0;
        for (int j = tid; j < 1024; j += 256) {
            if (sv[j] > m) { m = sv[j]; mi = j; }
        }
        rv[tid] = m; ri[tid] = mi;
        __syncthreads();
        for (int s = 128; s > 0; s >>= 1) {
            if (tid < s && rv[tid + s] > rv[tid]) { rv[tid] = rv[tid + s]; ri[tid] = ri[tid + s]; }
            __syncthreads();
        }
        if (tid == 0) {
            int pos = ri[0];
            g_topk[b][r][sel] = si[pos];
            sv[pos] = NEG_INF;
        }
        __syncthreads();
    }
}

// ---------------- gather H + RH dots ----------------
// grid (4, 128, B), 256 threads
__global__ void gather_h_kernel(const float* __restrict__ teacher) {
    __shared__ float sb[256];
    int k = blockIdx.x, r = blockIdx.y, b = blockIdx.z;
    int idx = g_topk[b][r][k];
    int f = 1 + 2 * (idx >> 11);
    int p = idx & 2047;
    const float* src = teacher + (((size_t)b * 8 + f) * PP + p) * D;
    float* dst = &g_X[b][256 + r * 4 + k][0];
    const float* rt = &g_X[b][r][0];
    const float* rs = &g_X[b][128 + r][0];
    int tid = threadIdx.x;
    float4 v  = ld4(src + tid * 4);
    float4 t4 = ld4(rt + tid * 4);
    float4 s4 = ld4(rs + tid * 4);
    *reinterpret_cast<float4*>(dst + tid * 4) = v;
    float st = v.x * t4.x + v.y * t4.y + v.z * t4.z + v.w * t4.w;
    float ss = v.x * s4.x + v.y * s4.y + v.z * s4.z + v.w * s4.w;
    st = block_reduce_sum(st, sb, 256);
    ss = block_reduce_sum(ss, sb, 256);
    if (tid == 0) {
        float hn2 = g_en2[b][idx];
        g_RHt[b][r][k] = st;
        g_RHs[b][r][k] = ss;
        g_Hn2[b][r][k] = hn2;
        g_nRHt[b][r][k] = fmaxf(sqrtf(fmaxf(g_rtn2[b][r] + hn2 - 2.f * st, 0.f)), EPSA);
        g_nRHs[b][r][k] = fmaxf(sqrtf(fmaxf(g_rsn2[b][r] + hn2 - 2.f * ss, 0.f)), EPSA);
    }
}

// ---------------- elementwise angle + huber loss ----------------
__device__ __forceinline__ float huber(float e) {
    float ae = fabsf(e);
    return (ae <= 1.0f) ? 0.5f * e * e : (ae - 0.5f);
}

// grid (128, B, 3): r, b, pair; 128 threads (thread = s)
__global__ void loss_kernel() {
    __shared__ float sb[128];
    int r = blockIdx.x, b = blockIdx.y, pair = blockIdx.z;
    int s = threadIdx.x;

    float rtn2 = g_rtn2[b][r];
    float rsn2 = g_rsn2[b][r];
    float sht2 = g_shn2[pair][b][0][s];
    float shs2 = g_shn2[pair][b][1][s];
    const float* Tb = &g_T[pair][b][0][0];

    float RSht = Tb[(size_t)r * 256 + s];
    float RShs = Tb[(size_t)(128 + r) * 256 + 128 + s];
    float nRSht = fmaxf(sqrtf(fmaxf(rtn2 + sht2 - 2.f * RSht, 0.f)), EPSA);
    float nRShs = fmaxf(sqrtf(fmaxf(rsn2 + shs2 - 2.f * RShs, 0.f)), EPSA);

    float acc = 0.f;
#pragma unroll
    for (int k = 0; k < KTOP; k++) {
        float RHt = g_RHt[b][r][k];
        float RHs = g_RHs[b][r][k];
        float hn2 = g_Hn2[b][r][k];
        float nRHt = g_nRHt[b][r][k];
        float nRHs = g_nRHs[b][r][k];
        float HSht = Tb[(size_t)(256 + r * 4 + k) * 256 + s];
        float HShs = Tb[(size_t)(256 + r * 4 + k) * 256 + 128 + s];
        float nHSht = fmaxf(sqrtf(fmaxf(hn2 + sht2 - 2.f * HSht, 0.f)), EPSA);
        float nHShs = fmaxf(sqrtf(fmaxf(hn2 + shs2 - 2.f * HShs, 0.f)), EPSA);

        float a1t = (HSht - RSht - RHt + rtn2) / (nRSht * nRHt);
        float a1s = (HShs - RShs - RHs + rsn2) / (nRShs * nRHs);
        acc += huber(a1s - a1t);

        float a2t = (RSht - RHt - HSht + hn2) / (nRHt * nHSht);
        float a2s = (RShs - RHs - HShs + hn2) / (nRHs * nHShs);
        acc += huber(a2s - a2t);

        float a3t = (RHt - RSht - HSht + sht2) / (nRSht * nHSht);
        float a3s = (RHs - RShs - HShs + shs2) / (nRShs * nHShs);
        acc += huber(a3s - a3t);
    }
    acc = block_reduce_sum(acc, sb, 128);
    if (threadIdx.x == 0) {
        g_partial[(pair * BB + b) * RR + r] = acc;
    }
}

// single block, 256 threads: deterministic final reduction
__global__ void finalize_kernel(float* __restrict__ out) {
    __shared__ float sb[256];
    int tid = threadIdx.x;
    float v = g_partial[tid] + g_partial[tid + 256] + g_partial[tid + 512];
    v = block_reduce_sum(v, sb, 256);
    if (tid == 0) {
        out[0] = v / (float)(NPAIR * BB * RR * SS * KTOP);
    }
}

// ---------------- launch ----------------
extern "C" void kernel_launch(void* const* d_in, const int* in_sizes, int n_in,
                              void* d_out, int out_size) {
    const float* teacher = (const float*)d_in[0];
    const float* student = (const float*)d_in[1];
    const int* ref_perm = (const int*)d_in[2];
    const int* shared_perm = (const int*)d_in[3];
    float* out = (float*)d_out;

    gather_refs_kernel<<<dim3(RR, BB, 2), 256>>>(teacher, student, ref_perm);
    gather_sh_kernel<<<dim3(SS, BB, 6), 256>>>(teacher, student, shared_perm);
    extra_norm_kernel<<<dim3(EE, BB), 256>>>(teacher);
    sim_gemm_kernel<<<dim3(64, BB), 256>>>(teacher);
    topk_kernel<<<dim3(RR, BB), 256>>>();
    gather_h_kernel<<<dim3(KTOP, RR, BB), 256>>>(teacher);
    t_gemm_kernel<<<dim3(2, 6, 6), 256>>>();
    loss_kernel<<<dim3(RR, BB, NPAIR), 128>>>();
    finalize_kernel<<<1, 256>>>(out);
}

// round 6
// speedup vs baseline: 1.5119x; 1.5119x over previous
#include <cuda_runtime.h>
#include <cuda_bf16.h>
#include <cstdint>

// Problem constants
#define D      1024
#define PP     2048
#define BB     2
#define RR     128
#define SS     128
#define KTOP   4
#define EE     8192        // 4 frames * 2048
#define NPAIR  3
#define EPSA   1e-8f
#define NEG_INF -3.402823466e38f

// tcgen05 is legal only in arch-SPECIFIC (sm_103a) or family (sm_103f) passes.
// A plain compute_103/sm_103 pass must compile the FFMA2 fallback instead.
#if defined(__CUDA_ARCH__) && (defined(__CUDA_ARCH_FEAT_SM103_ALL) || \
                               defined(__CUDA_ARCH_FEAT_SM100_ALL) || \
                               defined(__CUDA_ARCH_SPECIFIC__) ||     \
                               defined(__CUDA_ARCH_FAMILY_SPECIFIC__))
#define TC_OK 1
#else
#define TC_OK 0
#endif

// ---------------- static device scratch ----------------
__device__ float g_X[BB][768][D];            // rows 0..127 ref_t, 128..255 ref_s, 256..767 H (r*4+k)
__device__ float g_Sh[NPAIR][BB][256][D];    // rows 0..127 Sh_t, 128..255 Sh_s
__device__ float g_sim[BB][RR][EE];
__device__ float g_T[NPAIR][BB][768][256];
__device__ float g_en2[BB][EE];
__device__ float g_rtn2[BB][RR];
__device__ float g_rsn2[BB][RR];
__device__ float g_shn2[NPAIR][BB][2][SS];
__device__ float g_Hn2[BB][RR][KTOP];
__device__ float g_RHt[BB][RR][KTOP];
__device__ float g_RHs[BB][RR][KTOP];
__device__ float g_nRHt[BB][RR][KTOP];
__device__ float g_nRHs[BB][RR][KTOP];
__device__ int   g_topk[BB][RR][KTOP];
__device__ float g_partial[NPAIR * BB * RR];

// ---------------- helpers ----------------
__device__ __forceinline__ float4 ld4(const float* p) {
    return *reinterpret_cast<const float4*>(p);
}

__device__ __forceinline__ float block_reduce_sum(float v, float* sb, int n) {
    int tid = threadIdx.x;
    sb[tid] = v;
    __syncthreads();
    for (int s = n >> 1; s > 0; s >>= 1) {
        if (tid < s) sb[tid] += sb[tid + s];
        __syncthreads();
    }
    float r = sb[0];
    __syncthreads();
    return r;
}

#if TC_OK
__device__ __forceinline__ uint32_t s2u(const void* p) {
    uint32_t a;
    asm("{ .reg .u64 t; cvta.to.shared.u64 t, %1; cvt.u32.u64 %0, t; }" : "=r"(a) : "l"(p));
    return a;
}

__device__ __forceinline__ bool elect1() {
    uint32_t p;
    asm volatile("{\n\t.reg .pred p;\n\telect.sync _|p, 0xFFFFFFFF;\n\tselp.b32 %0,1,0,p;\n\t}"
                 : "=r"(p));
    return p != 0;
}

// SW128 K-major descriptor (128B rows, LBO=1, SBO=64, Blackwell version bit)
__device__ __forceinline__ uint64_t mk_desc(uint32_t addr) {
    const uint64_t base = (2ull << 61) | (1ull << 46) | (64ull << 32) | (1ull << 16);
    return base | ((uint64_t)(addr >> 4) & 0x3FFF);
}

// idesc: dtype=F32, atype=btype=BF16, N=128, M=128, cg1
#define TC_IDESC 0x8200490u

__device__ __forceinline__ void mma_ss(uint32_t d, uint64_t ad, uint64_t bd, uint32_t en) {
    asm volatile(
        "{\n\t.reg .pred p;\n\tsetp.ne.u32 p, %5, 0;\n\t"
        "tcgen05.mma.cta_group::1.kind::f16 [%0], %1, %2, %3, {%4,%4,%4,%4}, p;\n\t}"
        :: "r"(d), "l"(ad), "l"(bd), "r"(TC_IDESC), "r"(0u), "r"(en)
        : "memory");
}

__device__ __forceinline__ void mbar_init(uint32_t a, uint32_t c) {
    asm volatile("mbarrier.init.shared.b64 [%0], %1;" :: "r"(a), "r"(c) : "memory");
}
__device__ __forceinline__ void mbar_wait(uint32_t a, uint32_t parity) {
    uint32_t done = 0;
    while (!done) {
        asm volatile(
            "{\n\t.reg .pred p;\n\t"
            "mbarrier.try_wait.parity.acquire.cta.shared::cta.b64 p, [%1], %2, 0x989680;\n\t"
            "selp.b32 %0,1,0,p;\n\t}"
            : "=r"(done) : "r"(a), "r"(parity) : "memory");
    }
}
__device__ __forceinline__ void tc_commit(uint32_t mbar) {
    asm volatile("tcgen05.commit.cta_group::1.mbarrier::arrive::one.shared::cluster.b64 [%0];"
                 :: "r"(mbar) : "memory");
}

#define TC_LD_X32(r, tmem_addr) \
    asm volatile( \
        "tcgen05.ld.sync.aligned.32x32b.x32.b32 " \
        "{%0, %1, %2, %3, %4, %5, %6, %7, " \
        " %8, %9, %10, %11, %12, %13, %14, %15, " \
        " %16, %17, %18, %19, %20, %21, %22, %23, " \
        " %24, %25, %26, %27, %28, %29, %30, %31}, [%32];" \
        : "=r"((r)[0]),  "=r"((r)[1]),  "=r"((r)[2]),  "=r"((r)[3]), \
          "=r"((r)[4]),  "=r"((r)[5]),  "=r"((r)[6]),  "=r"((r)[7]), \
          "=r"((r)[8]),  "=r"((r)[9]),  "=r"((r)[10]), "=r"((r)[11]), \
          "=r"((r)[12]), "=r"((r)[13]), "=r"((r)[14]), "=r"((r)[15]), \
          "=r"((r)[16]), "=r"((r)[17]), "=r"((r)[18]), "=r"((r)[19]), \
          "=r"((r)[20]), "=r"((r)[21]), "=r"((r)[22]), "=r"((r)[23]), \
          "=r"((r)[24]), "=r"((r)[25]), "=r"((r)[26]), "=r"((r)[27]), \
          "=r"((r)[28]), "=r"((r)[29]), "=r"((r)[30]), "=r"((r)[31]) \
        : "r"(tmem_addr))

// split (a,b) into packed bf16 hi + bf16 lo
__device__ __forceinline__ void cvt2(float a, float b, uint32_t& hi, uint32_t& lo) {
    __nv_bfloat16 ah = __float2bfloat16(a), bh = __float2bfloat16(b);
    float ar = a - __bfloat162float(ah), br = b - __bfloat162float(bh);
    __nv_bfloat16 al = __float2bfloat16(ar), bl = __float2bfloat16(br);
    hi = (uint32_t)__bfloat16_as_ushort(ah) | ((uint32_t)__bfloat16_as_ushort(bh) << 16);
    lo = (uint32_t)__bfloat16_as_ushort(al) | ((uint32_t)__bfloat16_as_ushort(bl) << 16);
}
#else
// packed f32x2 FMA (sm_100+ plain target): 2 fp32 FMAs per fma-pipe issue
__device__ __forceinline__ unsigned long long dup2(float a) {
    unsigned long long r;
    asm("mov.b64 %0, {%1, %1};" : "=l"(r) : "f"(a));
    return r;
}
__device__ __forceinline__ unsigned long long fma2(unsigned long long a, unsigned long long b,
                                                   unsigned long long c) {
    unsigned long long d;
    asm("fma.rn.f32x2 %0, %1, %2, %3;" : "=l"(d) : "l"(a), "l"(b), "l"(c));
    return d;
}
#endif

// ---------------- gather kernels ----------------
__global__ void gather_refs_kernel(const float* __restrict__ teacher,
                                   const float* __restrict__ student,
                                   const int* __restrict__ ref_perm) {
    __shared__ float sb[256];
    int r = blockIdx.x, b = blockIdx.y, w = blockIdx.z;
    int p = ref_perm[r];
    const float* src = (w == 0)
        ? teacher + (((size_t)b * 8 + 0) * PP + p) * D
        : student + (((size_t)b * 4 + 0) * PP + p) * D;
    float* dst = &g_X[b][w * 128 + r][0];
    int tid = threadIdx.x;
    float4 v = ld4(src + tid * 4);
    *reinterpret_cast<float4*>(dst + tid * 4) = v;
    float ss = v.x * v.x + v.y * v.y + v.z * v.z + v.w * v.w;
    ss = block_reduce_sum(ss, sb, 256);
    if (tid == 0) {
        if (w == 0) g_rtn2[b][r] = ss; else g_rsn2[b][r] = ss;
    }
}

__global__ void gather_sh_kernel(const float* __restrict__ teacher,
                                 const float* __restrict__ student,
                                 const int* __restrict__ shared_perm) {
    __shared__ float sb[256];
    int s = blockIdx.x, b = blockIdx.y, z = blockIdx.z;
    int pair = z >> 1, w = z & 1;
    int p = shared_perm[s];
    const float* src = (w == 0)
        ? teacher + (((size_t)b * 8 + 2 * (pair + 1)) * PP + p) * D
        : student + (((size_t)b * 4 + (pair + 1)) * PP + p) * D;
    float* dst = &g_Sh[pair][b][w * 128 + s][0];
    int tid = threadIdx.x;
    float4 v = ld4(src + tid * 4);
    *reinterpret_cast<float4*>(dst + tid * 4) = v;
    float ss = v.x * v.x + v.y * v.y + v.z * v.z + v.w * v.w;
    ss = block_reduce_sum(ss, sb, 256);
    if (tid == 0) g_shn2[pair][b][w][s] = ss;
}

// ---------------- unified 128x128x1024 GEMM ----------------
// C[128,128] = A[128,1024] . B[128,1024]^T.
// SCALE: pre-pass computes |B_row|^2 into smem + en2g; epilogue scales
// column n by rsqrt(max(en2[n], 1e-24)).
// Dynamic smem layout (both paths):
//  [0]        tmem ptr (TC)
//  [16,32)    2 mbarriers (TC)
//  [64,576)   en2[128] floats
//  [1024, ..) TC: slot0/slot1 staging (A_hi A_lo B_hi B_lo, 16K each)
//             FB: As[16][132], Bs[16][132]
#define SMEM_TC_TOTAL (1024 + 2 * 65536)

template <bool SCALE>
__device__ __forceinline__ void gemm_any(const float* __restrict__ A,
                                         const float* __restrict__ Bsrc,
                                         float* __restrict__ C, int ldc,
                                         float* __restrict__ en2g,
                                         char* sm) {
    const int tid = threadIdx.x;
    float* sm_en2 = reinterpret_cast<float*>(sm + 64);

#if TC_OK
    const int wid = tid >> 5;
    uint32_t sbase = s2u(sm);
    if (wid == 0) {
        asm volatile("tcgen05.alloc.cta_group::1.sync.aligned.shared::cta.b32 [%0], %1;"
                     :: "r"(sbase), "r"(128u) : "memory");
        asm volatile("tcgen05.relinquish_alloc_permit.cta_group::1.sync.aligned;");
    }
    if (tid == 0) { mbar_init(sbase + 16, 1); mbar_init(sbase + 24, 1); }
#endif

    if (SCALE) {
        // squared norms of B rows (= sim column scales, and g_en2 for later stages)
        int r = tid >> 1, h = tid & 1;
        const float* p = Bsrc + (size_t)r * D + h * 512;
        float a0 = 0.f, a1 = 0.f, a2 = 0.f, a3 = 0.f;
        for (int i = 0; i < 128; i++) {
            float4 x = ld4(p + i * 4);
            a0 = fmaf(x.x, x.x, a0);
            a1 = fmaf(x.y, x.y, a1);
            a2 = fmaf(x.z, x.z, a2);
            a3 = fmaf(x.w, x.w, a3);
        }
        float ssum = (a0 + a1) + (a2 + a3);
        ssum += __shfl_xor_sync(0xffffffffu, ssum, 1);
        if (h == 0) { sm_en2[r] = ssum; en2g[r] = ssum; }
    }
    __syncthreads();

#if TC_OK
    // ---------------- tcgen05 path: bf16 hi/lo 3-product split ----------------
    uint32_t tmem;
    asm volatile("ld.shared.b32 %0, [%1];" : "=r"(tmem) : "r"(sbase));

    for (int kt = 0; kt < 16; ++kt) {
        int slot = kt & 1;
        uint32_t stg = 1024u + (uint32_t)slot * 65536u;
        if (kt >= 2) mbar_wait(sbase + 16 + slot * 8, ((kt - 2) >> 1) & 1);

        const float* srcA = A + kt * 64;
        const float* srcB = Bsrc + kt * 64;
#pragma unroll
        for (int t = tid; t < 2048; t += 256) {
            int mat = t >> 10;
            int r = (t >> 3) & 127;
            int c = t & 7;
            const float* src = (mat ? srcB : srcA) + (size_t)r * D + c * 8;
            float4 x = ld4(src);
            float4 y = ld4(src + 4);
            uint4 hi, lo;
            cvt2(x.x, x.y, hi.x, lo.x);
            cvt2(x.z, x.w, hi.y, lo.y);
            cvt2(y.x, y.y, hi.z, lo.z);
            cvt2(y.z, y.w, hi.w, lo.w);
            uint32_t off = ((uint32_t)r << 7) + ((uint32_t)c << 4);
            uint32_t sw = off ^ ((off >> 3) & 0x70);
            char* tb = sm + stg + mat * 32768;
            *reinterpret_cast<uint4*>(tb + sw) = hi;
            *reinterpret_cast<uint4*>(tb + 16384 + sw) = lo;
        }
        asm volatile("fence.proxy.async.shared::cta;" ::: "memory");
        __syncthreads();

        if (wid == 0 && elect1()) {
            uint32_t aH = sbase + stg;
            uint64_t dAH = mk_desc(aH);
            uint64_t dAL = mk_desc(aH + 16384);
            uint64_t dBH = mk_desc(aH + 32768);
            uint64_t dBL = mk_desc(aH + 49152);
#pragma unroll
            for (int kc = 0; kc < 4; ++kc) {
                mma_ss(tmem, dAH + kc * 2, dBH + kc * 2, (kt == 0 && kc == 0) ? 0u : 1u);
                mma_ss(tmem, dAH + kc * 2, dBL + kc * 2, 1u);
                mma_ss(tmem, dAL + kc * 2, dBH + kc * 2, 1u);
            }
            tc_commit(sbase + 16 + slot * 8);
        }
    }

    // last commit on slot1 is its 8th -> completes phase 7 -> parity 1
    mbar_wait(sbase + 24, 1);
    asm volatile("tcgen05.fence::after_thread_sync;" ::: "memory");

    if (tid < 128) {
        int l = tid & 31;
        float* Crow = C + (size_t)(wid * 32 + l) * ldc;
#pragma unroll
        for (int cb = 0; cb < 128; cb += 32) {
            uint32_t r[32];
            TC_LD_X32(r, tmem + cb);
            asm volatile("tcgen05.wait::ld.sync.aligned;" ::: "memory");
#pragma unroll
            for (int c = 0; c < 32; c += 4) {
                float4 o;
                o.x = __uint_as_float(r[c + 0]);
                o.y = __uint_as_float(r[c + 1]);
                o.z = __uint_as_float(r[c + 2]);
                o.w = __uint_as_float(r[c + 3]);
                if (SCALE) {
                    o.x *= rsqrtf(fmaxf(sm_en2[cb + c + 0], 1e-24f));
                    o.y *= rsqrtf(fmaxf(sm_en2[cb + c + 1], 1e-24f));
                    o.z *= rsqrtf(fmaxf(sm_en2[cb + c + 2], 1e-24f));
                    o.w *= rsqrtf(fmaxf(sm_en2[cb + c + 3], 1e-24f));
                }
                *reinterpret_cast<float4*>(Crow + cb + c) = o;
            }
        }
    }
    __syncthreads();
    if (wid == 0) {
        asm volatile("tcgen05.dealloc.cta_group::1.sync.aligned.b32 %0, %1;"
                     :: "r"(tmem), "r"(128u));
    }
#else
    // ---------------- fallback path: FFMA2 (fma.rn.f32x2) ----------------
    float (*As)[132] = reinterpret_cast<float (*)[132]>(sm + 1024);
    float (*Bs)[132] = reinterpret_cast<float (*)[132]>(sm + 1024 + 16 * 132 * 4);

    int tx = tid & 15;
    int ty = tid >> 4;
    int r0 = tid >> 2;
    int kq = tid & 3;
    int r1 = r0 + 64;

    unsigned long long acc[8][4];
#pragma unroll
    for (int i = 0; i < 8; i++)
#pragma unroll
        for (int j = 0; j < 4; j++) acc[i][j] = 0ull;

    const float* Ap0 = A + (size_t)r0 * D + kq * 4;
    const float* Ap1 = A + (size_t)r1 * D + kq * 4;
    const float* Bp0 = Bsrc + (size_t)r0 * D + kq * 4;
    const float* Bp1 = Bsrc + (size_t)r1 * D + kq * 4;

    float4 ra0 = ld4(Ap0);
    float4 ra1 = ld4(Ap1);
    float4 rb0 = ld4(Bp0);
    float4 rb1 = ld4(Bp1);

    for (int kt = 0; kt < 64; ++kt) {
        int kb = kq * 4;
        As[kb + 0][r0] = ra0.x; As[kb + 1][r0] = ra0.y; As[kb + 2][r0] = ra0.z; As[kb + 3][r0] = ra0.w;
        As[kb + 0][r1] = ra1.x; As[kb + 1][r1] = ra1.y; As[kb + 2][r1] = ra1.z; As[kb + 3][r1] = ra1.w;
        Bs[kb + 0][r0] = rb0.x; Bs[kb + 1][r0] = rb0.y; Bs[kb + 2][r0] = rb0.z; Bs[kb + 3][r0] = rb0.w;
        Bs[kb + 0][r1] = rb1.x; Bs[kb + 1][r1] = rb1.y; Bs[kb + 2][r1] = rb1.z; Bs[kb + 3][r1] = rb1.w;
        __syncthreads();

        if (kt < 63) {
            int ko = (kt + 1) * 16;
            ra0 = ld4(Ap0 + ko);
            ra1 = ld4(Ap1 + ko);
            rb0 = ld4(Bp0 + ko);
            rb1 = ld4(Bp1 + ko);
        }

#pragma unroll
        for (int kk = 0; kk < 16; ++kk) {
            float4 af0 = ld4(&As[kk][ty * 4]);
            float4 af1 = ld4(&As[kk][64 + ty * 4]);
            ulonglong2 bl0 = *reinterpret_cast<const ulonglong2*>(&Bs[kk][tx * 4]);
            ulonglong2 bl1 = *reinterpret_cast<const ulonglong2*>(&Bs[kk][64 + tx * 4]);
            unsigned long long av[8];
            av[0] = dup2(af0.x); av[1] = dup2(af0.y); av[2] = dup2(af0.z); av[3] = dup2(af0.w);
            av[4] = dup2(af1.x); av[5] = dup2(af1.y); av[6] = dup2(af1.z); av[7] = dup2(af1.w);
            unsigned long long bv[4] = {bl0.x, bl0.y, bl1.x, bl1.y};
#pragma unroll
            for (int i = 0; i < 8; i++)
#pragma unroll
                for (int j = 0; j < 4; j++) acc[i][j] = fma2(av[i], bv[j], acc[i][j]);
        }
        __syncthreads();
    }

    float inv0x = 1.f, inv0y = 1.f, inv0z = 1.f, inv0w = 1.f;
    float inv1x = 1.f, inv1y = 1.f, inv1z = 1.f, inv1w = 1.f;
    if (SCALE) {
        float4 c0 = ld4(sm_en2 + tx * 4);
        float4 c1 = ld4(sm_en2 + 64 + tx * 4);
        inv0x = rsqrtf(fmaxf(c0.x, 1e-24f)); inv0y = rsqrtf(fmaxf(c0.y, 1e-24f));
        inv0z = rsqrtf(fmaxf(c0.z, 1e-24f)); inv0w = rsqrtf(fmaxf(c0.w, 1e-24f));
        inv1x = rsqrtf(fmaxf(c1.x, 1e-24f)); inv1y = rsqrtf(fmaxf(c1.y, 1e-24f));
        inv1z = rsqrtf(fmaxf(c1.z, 1e-24f)); inv1w = rsqrtf(fmaxf(c1.w, 1e-24f));
    }
    union U { unsigned long long u; float2 f; };
#pragma unroll
    for (int ri = 0; ri < 8; ri++) {
        int m = (ri < 4) ? (ty * 4 + ri) : (64 + ty * 4 + (ri - 4));
        float* Cr = C + (size_t)m * ldc;
        U u0, u1, u2, u3;
        u0.u = acc[ri][0]; u1.u = acc[ri][1]; u2.u = acc[ri][2]; u3.u = acc[ri][3];
        float4 o0, o1;
        o0.x = u0.f.x; o0.y = u0.f.y; o0.z = u1.f.x; o0.w = u1.f.y;
        o1.x = u2.f.x; o1.y = u2.f.y; o1.z = u3.f.x; o1.w = u3.f.y;
        if (SCALE) {
            o0.x *= inv0x; o0.y *= inv0y; o0.z *= inv0z; o0.w *= inv0w;
            o1.x *= inv1x; o1.y *= inv1y; o1.z *= inv1z; o1.w *= inv1w;
        }
        *reinterpret_cast<float4*>(Cr + tx * 4) = o0;
        *reinterpret_cast<float4*>(Cr + 64 + tx * 4) = o1;
    }
#endif
}

// sim: C tile = ref_t . extra^T scaled by rsqrt(|extra|^2). grid (64, B)
__global__ __launch_bounds__(256, 1) void sim_tc_kernel(const float* __restrict__ teacher) {
    extern __shared__ char sm[];
    int b = blockIdx.y;
    int n0 = blockIdx.x * 128;
    int fc = n0 >> 11;
    const float* A = &g_X[b][0][0];
    const float* B = teacher + (((size_t)b * 8 + 1 + 2 * fc) * PP + (n0 & 2047)) * D;
    gemm_any<true>(A, B, &g_sim[b][0][n0], EE, &g_en2[b][n0], sm);
}

// T = [ref_t; ref_s; H] . [Sh_t; Sh_s]^T. grid (2, 6, 6): (n-tile, m-tile, pair*2+b)
__global__ __launch_bounds__(256, 1) void t_tc_kernel() {
    extern __shared__ char sm[];
    int z = blockIdx.z;
    int pair = z >> 1, b = z & 1;
    const float* A = &g_X[b][blockIdx.y * 128][0];
    const float* B = &g_Sh[pair][b][blockIdx.x * 128][0];
    float* C = &g_T[pair][b][blockIdx.y * 128][blockIdx.x * 128];
    gemm_any<false>(A, B, C, 256, nullptr, sm);
}

// ---------------- top-k ----------------
__global__ void topk_kernel() {
    int r = blockIdx.x, b = blockIdx.y;
    const float* row = &g_sim[b][r][0];
    int tid = threadIdx.x;

    float v0 = NEG_INF, v1 = NEG_INF, v2 = NEG_INF, v3 = NEG_INF;
    int i0 = 0, i1 = 0, i2 = 0, i3 = 0;
    for (int e = tid; e < EE; e += 256) {
        float x = row[e];
        if (x > v3) {
            if (x > v0)      { v3=v2;i3=i2; v2=v1;i2=i1; v1=v0;i1=i0; v0=x;i0=e; }
            else if (x > v1) { v3=v2;i3=i2; v2=v1;i2=i1; v1=x;i1=e; }
            else if (x > v2) { v3=v2;i3=i2; v2=x;i2=e; }
            else             { v3=x;i3=e; }
        }
    }
    __shared__ float sv[1024];
    __shared__ int   si[1024];
    __shared__ float rv[256];
    __shared__ int   ri[256];
    sv[tid*4+0]=v0; si[tid*4+0]=i0;
    sv[tid*4+1]=v1; si[tid*4+1]=i1;
    sv[tid*4+2]=v2; si[tid*4+2]=i2;
    sv[tid*4+3]=v3; si[tid*4+3]=i3;
    __syncthreads();

    for (int sel = 0; sel < KTOP; sel++) {
        float m = NEG_INF;
        int mi = 0;
        for (int j = tid; j < 1024; j += 256) {
            if (sv[j] > m) { m = sv[j]; mi = j; }
        }
        rv[tid] = m; ri[tid] = mi;
        __syncthreads();
        for (int s = 128; s > 0; s >>= 1) {
            if (tid < s && rv[tid + s] > rv[tid]) { rv[tid] = rv[tid + s]; ri[tid] = ri[tid + s]; }
            __syncthreads();
        }
        if (tid == 0) {
            int pos = ri[0];
            g_topk[b][r][sel] = si[pos];
            sv[pos] = NEG_INF;
        }
        __syncthreads();
    }
}

// ---------------- gather H + RH dots ----------------
__global__ void gather_h_kernel(const float* __restrict__ teacher) {
    __shared__ float sb[256];
    int k = blockIdx.x, r = blockIdx.y, b = blockIdx.z;
    int idx = g_topk[b][r][k];
    int f = 1 + 2 * (idx >> 11);
    int p = idx & 2047;
    const float* src = teacher + (((size_t)b * 8 + f) * PP + p) * D;
    float* dst = &g_X[b][256 + r * 4 + k][0];
    const float* rt = &g_X[b][r][0];
    const float* rs = &g_X[b][128 + r][0];
    int tid = threadIdx.x;
    float4 v  = ld4(src + tid * 4);
    float4 t4 = ld4(rt + tid * 4);
    float4 s4 = ld4(rs + tid * 4);
    *reinterpret_cast<float4*>(dst + tid * 4) = v;
    float st = v.x * t4.x + v.y * t4.y + v.z * t4.z + v.w * t4.w;
    float ss = v.x * s4.x + v.y * s4.y + v.z * s4.z + v.w * s4.w;
    st = block_reduce_sum(st, sb, 256);
    ss = block_reduce_sum(ss, sb, 256);
    if (tid == 0) {
        float hn2 = g_en2[b][idx];
        g_RHt[b][r][k] = st;
        g_RHs[b][r][k] = ss;
        g_Hn2[b][r][k] = hn2;
        g_nRHt[b][r][k] = fmaxf(sqrtf(fmaxf(g_rtn2[b][r] + hn2 - 2.f * st, 0.f)), EPSA);
        g_nRHs[b][r][k] = fmaxf(sqrtf(fmaxf(g_rsn2[b][r] + hn2 - 2.f * ss, 0.f)), EPSA);
    }
}

// ---------------- elementwise angle + huber loss ----------------
__device__ __forceinline__ float huber(float e) {
    float ae = fabsf(e);
    return (ae <= 1.0f) ? 0.5f * e * e : (ae - 0.5f);
}

__global__ void loss_kernel() {
    __shared__ float sb[128];
    int r = blockIdx.x, b = blockIdx.y, pair = blockIdx.z;
    int s = threadIdx.x;

    float rtn2 = g_rtn2[b][r];
    float rsn2 = g_rsn2[b][r];
    float sht2 = g_shn2[pair][b][0][s];
    float shs2 = g_shn2[pair][b][1][s];
    const float* Tb = &g_T[pair][b][0][0];

    float RSht = Tb[(size_t)r * 256 + s];
    float RShs = Tb[(size_t)(128 + r) * 256 + 128 + s];
    float nRSht = fmaxf(sqrtf(fmaxf(rtn2 + sht2 - 2.f * RSht, 0.f)), EPSA);
    float nRShs = fmaxf(sqrtf(fmaxf(rsn2 + shs2 - 2.f * RShs, 0.f)), EPSA);

    float acc = 0.f;
#pragma unroll
    for (int k = 0; k < KTOP; k++) {
        float RHt = g_RHt[b][r][k];
        float RHs = g_RHs[b][r][k];
        float hn2 = g_Hn2[b][r][k];
        float nRHt = g_nRHt[b][r][k];
        float nRHs = g_nRHs[b][r][k];
        float HSht = Tb[(size_t)(256 + r * 4 + k) * 256 + s];
        float HShs = Tb[(size_t)(256 + r * 4 + k) * 256 + 128 + s];
        float nHSht = fmaxf(sqrtf(fmaxf(hn2 + sht2 - 2.f * HSht, 0.f)), EPSA);
        float nHShs = fmaxf(sqrtf(fmaxf(hn2 + shs2 - 2.f * HShs, 0.f)), EPSA);

        float a1t = (HSht - RSht - RHt + rtn2) / (nRSht * nRHt);
        float a1s = (HShs - RShs - RHs + rsn2) / (nRShs * nRHs);
        acc += huber(a1s - a1t);

        float a2t = (RSht - RHt - HSht + hn2) / (nRHt * nHSht);
        float a2s = (RShs - RHs - HShs + hn2) / (nRHs * nHShs);
        acc += huber(a2s - a2t);

        float a3t = (RHt - RSht - HSht + sht2) / (nRSht * nHSht);
        float a3s = (RHs - RShs - HShs + shs2) / (nRShs * nHShs);
        acc += huber(a3s - a3t);
    }
    acc = block_reduce_sum(acc, sb, 128);
    if (threadIdx.x == 0) {
        g_partial[(pair * BB + b) * RR + r] = acc;
    }
}

__global__ void finalize_kernel(float* __restrict__ out) {
    __shared__ float sb[256];
    int tid = threadIdx.x;
    float v = g_partial[tid] + g_partial[tid + 256] + g_partial[tid + 512];
    v = block_reduce_sum(v, sb, 256);
    if (tid == 0) {
        out[0] = v / (float)(NPAIR * BB * RR * SS * KTOP);
    }
}

// ---------------- launch ----------------
extern "C" void kernel_launch(void* const* d_in, const int* in_sizes, int n_in,
                              void* d_out, int out_size) {
    const float* teacher = (const float*)d_in[0];
    const float* student = (const float*)d_in[1];
    const int* ref_perm = (const int*)d_in[2];
    const int* shared_perm = (const int*)d_in[3];
    float* out = (float*)d_out;

    cudaFuncSetAttribute(sim_tc_kernel, cudaFuncAttributeMaxDynamicSharedMemorySize, SMEM_TC_TOTAL);
    cudaFuncSetAttribute(t_tc_kernel, cudaFuncAttributeMaxDynamicSharedMemorySize, SMEM_TC_TOTAL);

    gather_refs_kernel<<<dim3(RR, BB, 2), 256>>>(teacher, student, ref_perm);
    gather_sh_kernel<<<dim3(SS, BB, 6), 256>>>(teacher, student, shared_perm);
    sim_tc_kernel<<<dim3(64, BB), 256, SMEM_TC_TOTAL>>>(teacher);
    topk_kernel<<<dim3(RR, BB), 256>>>();
    gather_h_kernel<<<dim3(KTOP, RR, BB), 256>>>(teacher);
    t_tc_kernel<<<dim3(2, 6, 6), 256, SMEM_TC_TOTAL>>>();
    loss_kernel<<<dim3(RR, BB, NPAIR), 128>>>();
    finalize_kernel<<<1, 256>>>(out);
}

// round 7
// speedup vs baseline: 2.6811x; 1.7733x over previous
#include <cuda_runtime.h>
#include <cuda_bf16.h>
#include <cstdint>

// Problem constants
#define D      1024
#define PP     2048
#define BB     2
#define RR     128
#define SS     128
#define KTOP   4
#define EE     8192        // 4 frames * 2048
#define NPAIR  3
#define NTILE  64          // sim column tiles of 128
#define EPSA   1e-8f
#define NEG_INF -3.402823466e38f

// tcgen05 is legal only in arch-SPECIFIC (sm_103a) or family passes.
#if defined(__CUDA_ARCH__) && (defined(__CUDA_ARCH_FEAT_SM103_ALL) || \
                               defined(__CUDA_ARCH_FEAT_SM100_ALL) || \
                               defined(__CUDA_ARCH_SPECIFIC__) ||     \
                               defined(__CUDA_ARCH_FAMILY_SPECIFIC__))
#define TC_OK 1
#else
#define TC_OK 0
#endif

// ---------------- static device scratch ----------------
__device__ float    g_X[BB][256][D];          // float ref_t (0..127), ref_s (128..255) for gather_h dots
__device__ uint32_t g_Xh[BB][768][D / 2];     // bf16x2 hi: ref_t, ref_s, H rows
__device__ uint32_t g_Xl[BB][768][D / 2];     // bf16x2 lo
__device__ uint32_t g_Shh[NPAIR][BB][256][D / 2];
__device__ uint32_t g_Shl[NPAIR][BB][256][D / 2];
__device__ float g_T[NPAIR][BB][768][256];
__device__ float g_en2[BB][EE];
__device__ float g_rtn2[BB][RR];
__device__ float g_rsn2[BB][RR];
__device__ float g_shn2[NPAIR][BB][2][SS];
__device__ float g_Hn2[BB][RR][KTOP];
__device__ float g_RHt[BB][RR][KTOP];
__device__ float g_RHs[BB][RR][KTOP];
__device__ float g_nRHt[BB][RR][KTOP];
__device__ float g_nRHs[BB][RR][KTOP];
__device__ int   g_topk[BB][RR][KTOP];
__device__ float g_cand_val[BB][NTILE][RR][KTOP];
__device__ int   g_cand_idx[BB][NTILE][RR][KTOP];
__device__ float g_partial[NPAIR * BB * RR];

// ---------------- helpers ----------------
__device__ __forceinline__ float4 ld4(const float* p) {
    return *reinterpret_cast<const float4*>(p);
}

__device__ __forceinline__ float block_reduce_sum(float v, float* sb, int n) {
    int tid = threadIdx.x;
    sb[tid] = v;
    __syncthreads();
    for (int s = n >> 1; s > 0; s >>= 1) {
        if (tid < s) sb[tid] += sb[tid + s];
        __syncthreads();
    }
    float r = sb[0];
    __syncthreads();
    return r;
}

// bf16 is the top 16 bits of f32: unpack via bit ops (no cvt needed)
__device__ __forceinline__ float bflo(uint32_t u) { return __uint_as_float(u << 16); }
__device__ __forceinline__ float bfhi(uint32_t u) { return __uint_as_float(u & 0xFFFF0000u); }

// split (a,b) -> packed bf16x2 hi + bf16x2 lo (a in low 16 bits)
__device__ __forceinline__ void cvt2(float a, float b, uint32_t& hi, uint32_t& lo) {
    asm("cvt.rn.bf16x2.f32 %0, %1, %2;" : "=r"(hi) : "f"(b), "f"(a));
    float ar = a - bflo(hi);
    float br = b - bfhi(hi);
    asm("cvt.rn.bf16x2.f32 %0, %1, %2;" : "=r"(lo) : "f"(br), "f"(ar));
}

// reconstruct 4 floats from packed hi/lo arrays at uint32 offset `off`
__device__ __forceinline__ float4 hilo4(const uint32_t* H, const uint32_t* L, size_t off) {
    uint2 h = *reinterpret_cast<const uint2*>(H + off);
    uint2 l = *reinterpret_cast<const uint2*>(L + off);
    float4 r;
    r.x = bflo(h.x) + bflo(l.x);
    r.y = bfhi(h.x) + bfhi(l.x);
    r.z = bflo(h.y) + bflo(l.y);
    r.w = bfhi(h.y) + bfhi(l.y);
    return r;
}

// descending top-4 insert
__device__ __forceinline__ void ins4(float x, int e,
                                     float& v0, float& v1, float& v2, float& v3,
                                     int& i0, int& i1, int& i2, int& i3) {
    if (x > v3) {
        if (x > v0)      { v3=v2;i3=i2; v2=v1;i2=i1; v1=v0;i1=i0; v0=x;i0=e; }
        else if (x > v1) { v3=v2;i3=i2; v2=v1;i2=i1; v1=x;i1=e; }
        else if (x > v2) { v3=v2;i3=i2; v2=x;i2=e; }
        else             { v3=x;i3=e; }
    }
}

#if TC_OK
__device__ __forceinline__ uint32_t s2u(const void* p) {
    uint32_t a;
    asm("{ .reg .u64 t; cvta.to.shared.u64 t, %1; cvt.u32.u64 %0, t; }" : "=r"(a) : "l"(p));
    return a;
}

__device__ __forceinline__ bool elect1() {
    uint32_t p;
    asm volatile("{\n\t.reg .pred p;\n\telect.sync _|p, 0xFFFFFFFF;\n\tselp.b32 %0,1,0,p;\n\t}"
                 : "=r"(p));
    return p != 0;
}

// SW128 K-major descriptor (128B rows, LBO=1, SBO=64, Blackwell version bit)
__device__ __forceinline__ uint64_t mk_desc(uint32_t addr) {
    const uint64_t base = (2ull << 61) | (1ull << 46) | (64ull << 32) | (1ull << 16);
    return base | ((uint64_t)(addr >> 4) & 0x3FFF);
}

// idesc: dtype=F32, atype=btype=BF16, N=128, M=128, cg1
#define TC_IDESC 0x8200490u

__device__ __forceinline__ void mma_ss(uint32_t d, uint64_t ad, uint64_t bd, uint32_t en) {
    asm volatile(
        "{\n\t.reg .pred p;\n\tsetp.ne.u32 p, %5, 0;\n\t"
        "tcgen05.mma.cta_group::1.kind::f16 [%0], %1, %2, %3, {%4,%4,%4,%4}, p;\n\t}"
        :: "r"(d), "l"(ad), "l"(bd), "r"(TC_IDESC), "r"(0u), "r"(en)
        : "memory");
}

__device__ __forceinline__ void mbar_init(uint32_t a, uint32_t c) {
    asm volatile("mbarrier.init.shared.b64 [%0], %1;" :: "r"(a), "r"(c) : "memory");
}
__device__ __forceinline__ void mbar_wait(uint32_t a, uint32_t parity) {
    uint32_t done = 0;
    while (!done) {
        asm volatile(
            "{\n\t.reg .pred p;\n\t"
            "mbarrier.try_wait.parity.acquire.cta.shared::cta.b64 p, [%1], %2, 0x989680;\n\t"
            "selp.b32 %0,1,0,p;\n\t}"
            : "=r"(done) : "r"(a), "r"(parity) : "memory");
    }
}
__device__ __forceinline__ void tc_commit(uint32_t mbar) {
    asm volatile("tcgen05.commit.cta_group::1.mbarrier::arrive::one.shared::cluster.b64 [%0];"
                 :: "r"(mbar) : "memory");
}

#define TC_LD_X32(r, tmem_addr) \
    asm volatile( \
        "tcgen05.ld.sync.aligned.32x32b.x32.b32 " \
        "{%0, %1, %2, %3, %4, %5, %6, %7, " \
        " %8, %9, %10, %11, %12, %13, %14, %15, " \
        " %16, %17, %18, %19, %20, %21, %22, %23, " \
        " %24, %25, %26, %27, %28, %29, %30, %31}, [%32];" \
        : "=r"((r)[0]),  "=r"((r)[1]),  "=r"((r)[2]),  "=r"((r)[3]), \
          "=r"((r)[4]),  "=r"((r)[5]),  "=r"((r)[6]),  "=r"((r)[7]), \
          "=r"((r)[8]),  "=r"((r)[9]),  "=r"((r)[10]), "=r"((r)[11]), \
          "=r"((r)[12]), "=r"((r)[13]), "=r"((r)[14]), "=r"((r)[15]), \
          "=r"((r)[16]), "=r"((r)[17]), "=r"((r)[18]), "=r"((r)[19]), \
          "=r"((r)[20]), "=r"((r)[21]), "=r"((r)[22]), "=r"((r)[23]), \
          "=r"((r)[24]), "=r"((r)[25]), "=r"((r)[26]), "=r"((r)[27]), \
          "=r"((r)[28]), "=r"((r)[29]), "=r"((r)[30]), "=r"((r)[31]) \
        : "r"(tmem_addr))
#else
// packed f32x2 FMA fallback
__device__ __forceinline__ unsigned long long dup2(float a) {
    unsigned long long r;
    asm("mov.b64 %0, {%1, %1};" : "=l"(r) : "f"(a));
    return r;
}
__device__ __forceinline__ unsigned long long fma2(unsigned long long a, unsigned long long b,
                                                   unsigned long long c) {
    unsigned long long d;
    asm("fma.rn.f32x2 %0, %1, %2, %3;" : "=l"(d) : "l"(a), "l"(b), "l"(c));
    return d;
}
#endif

// ---------------- gather kernels ----------------
// grid (128, B, 2): r, b, w (0=ref_t teacher f0, 1=ref_s student f0)
__global__ void gather_refs_kernel(const float* __restrict__ teacher,
                                   const float* __restrict__ student,
                                   const int* __restrict__ ref_perm) {
    __shared__ float sb[256];
    int r = blockIdx.x, b = blockIdx.y, w = blockIdx.z;
    int p = ref_perm[r];
    const float* src = (w == 0)
        ? teacher + (((size_t)b * 8 + 0) * PP + p) * D
        : student + (((size_t)b * 4 + 0) * PP + p) * D;
    int row = w * 128 + r;
    int tid = threadIdx.x;
    float4 v = ld4(src + tid * 4);
    *reinterpret_cast<float4*>(&g_X[b][row][tid * 4]) = v;
    uint2 hi, lo;
    cvt2(v.x, v.y, hi.x, lo.x);
    cvt2(v.z, v.w, hi.y, lo.y);
    *reinterpret_cast<uint2*>(&g_Xh[b][row][tid * 2]) = hi;
    *reinterpret_cast<uint2*>(&g_Xl[b][row][tid * 2]) = lo;
    float ss = v.x * v.x + v.y * v.y + v.z * v.z + v.w * v.w;
    ss = block_reduce_sum(ss, sb, 256);
    if (tid == 0) {
        if (w == 0) g_rtn2[b][r] = ss; else g_rsn2[b][r] = ss;
    }
}

// grid (128, B, 6): s, b, z=pair*2+w
__global__ void gather_sh_kernel(const float* __restrict__ teacher,
                                 const float* __restrict__ student,
                                 const int* __restrict__ shared_perm) {
    __shared__ float sb[256];
    int s = blockIdx.x, b = blockIdx.y, z = blockIdx.z;
    int pair = z >> 1, w = z & 1;
    int p = shared_perm[s];
    const float* src = (w == 0)
        ? teacher + (((size_t)b * 8 + 2 * (pair + 1)) * PP + p) * D
        : student + (((size_t)b * 4 + (pair + 1)) * PP + p) * D;
    int row = w * 128 + s;
    int tid = threadIdx.x;
    float4 v = ld4(src + tid * 4);
    uint2 hi, lo;
    cvt2(v.x, v.y, hi.x, lo.x);
    cvt2(v.z, v.w, hi.y, lo.y);
    *reinterpret_cast<uint2*>(&g_Shh[pair][b][row][tid * 2]) = hi;
    *reinterpret_cast<uint2*>(&g_Shl[pair][b][row][tid * 2]) = lo;
    float ss = v.x * v.x + v.y * v.y + v.z * v.z + v.w * v.w;
    ss = block_reduce_sum(ss, sb, 256);
    if (tid == 0) g_shn2[pair][b][w][s] = ss;
}

// ---------------- smem layout for GEMM kernels ----------------
//  [0]        tmem ptr (TC)
//  [16,32)    2 mbarriers (TC)
//  [64,576)   inv/en2[128] floats
//  [1024,..)  TC: slot0/slot1 staging (A_hi A_lo B_hi B_lo, 16K each) = 128K
//             FB: As[16][132], Bs[16][132] (~17K), Cs[128][128] at +66560 (64K)
#define SMEM_TC_TOTAL (1024 + 2 * 65536)

#if !TC_OK
// ---------------- FFMA2 fallback core (correctness path) ----------------
// C = A.B^T, A from hi/lo bf16 arrays; B raw floats or hi/lo. Result (scaled by
// sm_inv[col] if SCALE) written to smem Cs at sm+66560.
template <bool SCALE, bool B_RAW>
__device__ __forceinline__ void gemm_fb(const uint32_t* __restrict__ Ah,
                                        const uint32_t* __restrict__ Al,
                                        const float* __restrict__ Braw,
                                        const uint32_t* __restrict__ Bh,
                                        const uint32_t* __restrict__ Bl,
                                        const float* __restrict__ sm_inv,
                                        char* sm) {
    float (*As)[132] = reinterpret_cast<float (*)[132]>(sm + 1024);
    float (*Bs)[132] = reinterpret_cast<float (*)[132]>(sm + 1024 + 16 * 132 * 4);
    float (*Cs)[128] = reinterpret_cast<float (*)[128]>(sm + 66560);

    int tid = threadIdx.x;
    int tx = tid & 15, ty = tid >> 4;
    int r0 = tid >> 2, kq = tid & 3, r1 = r0 + 64;

    unsigned long long acc[8][4];
#pragma unroll
    for (int i = 0; i < 8; i++)
#pragma unroll
        for (int j = 0; j < 4; j++) acc[i][j] = 0ull;

    for (int kt = 0; kt < 64; ++kt) {
        size_t offA0 = (size_t)r0 * 512 + kq * 2 + kt * 8;
        size_t offA1 = (size_t)r1 * 512 + kq * 2 + kt * 8;
        float4 ra0 = hilo4(Ah, Al, offA0);
        float4 ra1 = hilo4(Ah, Al, offA1);
        float4 rb0, rb1;
        if (B_RAW) {
            rb0 = ld4(Braw + (size_t)r0 * D + kq * 4 + kt * 16);
            rb1 = ld4(Braw + (size_t)r1 * D + kq * 4 + kt * 16);
        } else {
            rb0 = hilo4(Bh, Bl, offA0);
            rb1 = hilo4(Bh, Bl, offA1);
        }
        int kb = kq * 4;
        As[kb + 0][r0] = ra0.x; As[kb + 1][r0] = ra0.y; As[kb + 2][r0] = ra0.z; As[kb + 3][r0] = ra0.w;
        As[kb + 0][r1] = ra1.x; As[kb + 1][r1] = ra1.y; As[kb + 2][r1] = ra1.z; As[kb + 3][r1] = ra1.w;
        Bs[kb + 0][r0] = rb0.x; Bs[kb + 1][r0] = rb0.y; Bs[kb + 2][r0] = rb0.z; Bs[kb + 3][r0] = rb0.w;
        Bs[kb + 0][r1] = rb1.x; Bs[kb + 1][r1] = rb1.y; Bs[kb + 2][r1] = rb1.z; Bs[kb + 3][r1] = rb1.w;
        __syncthreads();

#pragma unroll
        for (int kk = 0; kk < 16; ++kk) {
            float4 af0 = ld4(&As[kk][ty * 4]);
            float4 af1 = ld4(&As[kk][64 + ty * 4]);
            ulonglong2 bl0 = *reinterpret_cast<const ulonglong2*>(&Bs[kk][tx * 4]);
            ulonglong2 bl1 = *reinterpret_cast<const ulonglong2*>(&Bs[kk][64 + tx * 4]);
            unsigned long long av[8];
            av[0] = dup2(af0.x); av[1] = dup2(af0.y); av[2] = dup2(af0.z); av[3] = dup2(af0.w);
            av[4] = dup2(af1.x); av[5] = dup2(af1.y); av[6] = dup2(af1.z); av[7] = dup2(af1.w);
            unsigned long long bv[4] = {bl0.x, bl0.y, bl1.x, bl1.y};
#pragma unroll
            for (int i = 0; i < 8; i++)
#pragma unroll
                for (int j = 0; j < 4; j++) acc[i][j] = fma2(av[i], bv[j], acc[i][j]);
        }
        __syncthreads();
    }

    union U { unsigned long long u; float2 f; };
#pragma unroll
    for (int ri = 0; ri < 8; ri++) {
        int m = (ri < 4) ? (ty * 4 + ri) : (64 + ty * 4 + (ri - 4));
        U u0, u1, u2, u3;
        u0.u = acc[ri][0]; u1.u = acc[ri][1]; u2.u = acc[ri][2]; u3.u = acc[ri][3];
        float o[8] = {u0.f.x, u0.f.y, u1.f.x, u1.f.y, u2.f.x, u2.f.y, u3.f.x, u3.f.y};
#pragma unroll
        for (int j = 0; j < 8; j++) {
            int col = (j < 4) ? (tx * 4 + j) : (64 + tx * 4 + (j - 4));
            float x = o[j];
            if (SCALE) x *= sm_inv[col];
            Cs[m][col] = x;
        }
    }
}
#endif

// ---------------- sim GEMM: cand top-4 + en2, grid (64, B) ----------------
__global__ __launch_bounds__(256, 1) void sim_tc_kernel(const float* __restrict__ teacher) {
    extern __shared__ char sm[];
    const int tid = threadIdx.x;
    const int b = blockIdx.y;
    const int tile = blockIdx.x;
    const int n0 = tile * 128;
    const float* Bsrc = teacher + (((size_t)b * 8 + 1 + 2 * (n0 >> 11)) * PP + (n0 & 2047)) * D;
    const uint32_t* Ah = &g_Xh[b][0][0];
    const uint32_t* Al = &g_Xl[b][0][0];
    float* sm_inv = reinterpret_cast<float*>(sm + 64);

#if TC_OK
    const int wid = tid >> 5;
    uint32_t sbase = s2u(sm);
    if (wid == 0) {
        asm volatile("tcgen05.alloc.cta_group::1.sync.aligned.shared::cta.b32 [%0], %1;"
                     :: "r"(sbase), "r"(128u) : "memory");
        asm volatile("tcgen05.relinquish_alloc_permit.cta_group::1.sync.aligned;");
    }
    if (tid == 0) { mbar_init(sbase + 16, 1); mbar_init(sbase + 24, 1); }
    __syncthreads();

    uint32_t tmem;
    asm volatile("ld.shared.b32 %0, [%1];" : "=r"(tmem) : "r"(sbase));

    float sq[4] = {0.f, 0.f, 0.f, 0.f};
    const int bc = tid & 7;          // B column-group within row
    const int br_base = tid >> 3;    // B row base (0..31), +32*j

    for (int kt = 0; kt < 16; ++kt) {
        int slot = kt & 1;
        uint32_t stg = 1024u + (uint32_t)slot * 65536u;
        if (kt >= 2) mbar_wait(sbase + 16 + slot * 8, ((kt - 2) >> 1) & 1);

        // A: copy pre-converted hi/lo
#pragma unroll
        for (int i = 0; i < 4; i++) {
            int t = tid + 256 * i;
            int r = t >> 3, c = t & 7;
            size_t off = (size_t)r * 512 + kt * 32 + c * 4;
            uint4 hi = *reinterpret_cast<const uint4*>(Ah + off);
            uint4 lo = *reinterpret_cast<const uint4*>(Al + off);
            uint32_t o = ((uint32_t)r << 7) + ((uint32_t)c << 4);
            uint32_t sw = o ^ ((o >> 3) & 0x70);
            char* tb = sm + stg;
            *reinterpret_cast<uint4*>(tb + sw) = hi;
            *reinterpret_cast<uint4*>(tb + 16384 + sw) = lo;
        }
        // B: convert raw floats, accumulate squared norms
#pragma unroll
        for (int j = 0; j < 4; j++) {
            int r = br_base + 32 * j;
            const float* src = Bsrc + (size_t)r * D + bc * 8 + kt * 64;
            float4 x = ld4(src);
            float4 y = ld4(src + 4);
            sq[j] = fmaf(x.x, x.x, sq[j]); sq[j] = fmaf(x.y, x.y, sq[j]);
            sq[j] = fmaf(x.z, x.z, sq[j]); sq[j] = fmaf(x.w, x.w, sq[j]);
            sq[j] = fmaf(y.x, y.x, sq[j]); sq[j] = fmaf(y.y, y.y, sq[j]);
            sq[j] = fmaf(y.z, y.z, sq[j]); sq[j] = fmaf(y.w, y.w, sq[j]);
            uint4 hi, lo;
            cvt2(x.x, x.y, hi.x, lo.x);
            cvt2(x.z, x.w, hi.y, lo.y);
            cvt2(y.x, y.y, hi.z, lo.z);
            cvt2(y.z, y.w, hi.w, lo.w);
            uint32_t o = ((uint32_t)r << 7) + ((uint32_t)bc << 4);
            uint32_t sw = o ^ ((o >> 3) & 0x70);
            char* tb = sm + stg + 32768;
            *reinterpret_cast<uint4*>(tb + sw) = hi;
            *reinterpret_cast<uint4*>(tb + 16384 + sw) = lo;
        }
        asm volatile("fence.proxy.async.shared::cta;" ::: "memory");
        __syncthreads();

        if (wid == 0 && elect1()) {
            uint32_t aH = sbase + stg;
            uint64_t dAH = mk_desc(aH);
            uint64_t dAL = mk_desc(aH + 16384);
            uint64_t dBH = mk_desc(aH + 32768);
            uint64_t dBL = mk_desc(aH + 49152);
#pragma unroll
            for (int kc = 0; kc < 4; ++kc) {
                mma_ss(tmem, dAH + kc * 2, dBH + kc * 2, (kt == 0 && kc == 0) ? 0u : 1u);
                mma_ss(tmem, dAH + kc * 2, dBL + kc * 2, 1u);
                mma_ss(tmem, dAL + kc * 2, dBH + kc * 2, 1u);
            }
            tc_commit(sbase + 16 + slot * 8);
        }
    }

    // en2: reduce sq over 8 column-groups (lanes xor 1,2,4 stay in group)
#pragma unroll
    for (int j = 0; j < 4; j++) {
        float s = sq[j];
        s += __shfl_xor_sync(0xffffffffu, s, 1);
        s += __shfl_xor_sync(0xffffffffu, s, 2);
        s += __shfl_xor_sync(0xffffffffu, s, 4);
        if (bc == 0) {
            int r = br_base + 32 * j;
            g_en2[b][n0 + r] = s;
            sm_inv[r] = rsqrtf(fmaxf(s, 1e-24f));
        }
    }

    mbar_wait(sbase + 24, 1);
    asm volatile("tcgen05.fence::after_thread_sync;" ::: "memory");
    __syncthreads();

    if (tid < 128) {
        int row = tid;   // warp w covers TMEM rows w*32.., lane order => row == tid
        float v0 = NEG_INF, v1 = NEG_INF, v2 = NEG_INF, v3 = NEG_INF;
        int i0 = 0, i1 = 0, i2 = 0, i3 = 0;
#pragma unroll
        for (int cb = 0; cb < 128; cb += 32) {
            uint32_t rr[32];
            TC_LD_X32(rr, tmem + cb);
            asm volatile("tcgen05.wait::ld.sync.aligned;" ::: "memory");
#pragma unroll
            for (int c = 0; c < 32; c++) {
                float x = __uint_as_float(rr[c]) * sm_inv[cb + c];
                ins4(x, n0 + cb + c, v0, v1, v2, v3, i0, i1, i2, i3);
            }
        }
        g_cand_val[b][tile][row][0] = v0; g_cand_idx[b][tile][row][0] = i0;
        g_cand_val[b][tile][row][1] = v1; g_cand_idx[b][tile][row][1] = i1;
        g_cand_val[b][tile][row][2] = v2; g_cand_idx[b][tile][row][2] = i2;
        g_cand_val[b][tile][row][3] = v3; g_cand_idx[b][tile][row][3] = i3;
    }
    __syncthreads();
    if (wid == 0) {
        asm volatile("tcgen05.dealloc.cta_group::1.sync.aligned.b32 %0, %1;"
                     :: "r"(tmem), "r"(128u));
    }
#else
    // FB: en2 pre-pass
    {
        int r = tid >> 1, h = tid & 1;
        const float* p = Bsrc + (size_t)r * D + h * 512;
        float a0 = 0.f, a1 = 0.f, a2 = 0.f, a3 = 0.f;
        for (int i = 0; i < 128; i++) {
            float4 x = ld4(p + i * 4);
            a0 = fmaf(x.x, x.x, a0); a1 = fmaf(x.y, x.y, a1);
            a2 = fmaf(x.z, x.z, a2); a3 = fmaf(x.w, x.w, a3);
        }
        float ssum = (a0 + a1) + (a2 + a3);
        ssum += __shfl_xor_sync(0xffffffffu, ssum, 1);
        if (h == 0) { g_en2[b][n0 + r] = ssum; sm_inv[r] = rsqrtf(fmaxf(ssum, 1e-24f)); }
    }
    __syncthreads();
    gemm_fb<true, true>(Ah, Al, Bsrc, nullptr, nullptr, sm_inv, sm);
    __syncthreads();
    if (tid < 128) {
        float (*Cs)[128] = reinterpret_cast<float (*)[128]>(sm + 66560);
        int row = tid;
        float v0 = NEG_INF, v1 = NEG_INF, v2 = NEG_INF, v3 = NEG_INF;
        int i0 = 0, i1 = 0, i2 = 0, i3 = 0;
        for (int c = 0; c < 128; c++)
            ins4(Cs[row][c], n0 + c, v0, v1, v2, v3, i0, i1, i2, i3);
        g_cand_val[b][tile][row][0] = v0; g_cand_idx[b][tile][row][0] = i0;
        g_cand_val[b][tile][row][1] = v1; g_cand_idx[b][tile][row][1] = i1;
        g_cand_val[b][tile][row][2] = v2; g_cand_idx[b][tile][row][2] = i2;
        g_cand_val[b][tile][row][3] = v3; g_cand_idx[b][tile][row][3] = i3;
    }
#endif
}

// ---------------- T GEMM: grid (2, 6, 6) ----------------
__global__ __launch_bounds__(256, 1) void t_tc_kernel() {
    extern __shared__ char sm[];
    const int tid = threadIdx.x;
    int z = blockIdx.z;
    int pair = z >> 1, b = z & 1;
    int m0 = blockIdx.y * 128;
    int nb0 = blockIdx.x * 128;
    const uint32_t* Ah = &g_Xh[b][m0][0];
    const uint32_t* Al = &g_Xl[b][m0][0];
    const uint32_t* Bh = &g_Shh[pair][b][nb0][0];
    const uint32_t* Bl = &g_Shl[pair][b][nb0][0];
    float* C = &g_T[pair][b][m0][nb0];

#if TC_OK
    const int wid = tid >> 5;
    uint32_t sbase = s2u(sm);
    if (wid == 0) {
        asm volatile("tcgen05.alloc.cta_group::1.sync.aligned.shared::cta.b32 [%0], %1;"
                     :: "r"(sbase), "r"(128u) : "memory");
        asm volatile("tcgen05.relinquish_alloc_permit.cta_group::1.sync.aligned;");
    }
    if (tid == 0) { mbar_init(sbase + 16, 1); mbar_init(sbase + 24, 1); }
    __syncthreads();

    uint32_t tmem;
    asm volatile("ld.shared.b32 %0, [%1];" : "=r"(tmem) : "r"(sbase));

    for (int kt = 0; kt < 16; ++kt) {
        int slot = kt & 1;
        uint32_t stg = 1024u + (uint32_t)slot * 65536u;
        if (kt >= 2) mbar_wait(sbase + 16 + slot * 8, ((kt - 2) >> 1) & 1);

#pragma unroll
        for (int i = 0; i < 8; i++) {
            int t = tid + 256 * i;
            int mat = t >> 10;
            int r = (t >> 3) & 127;
            int c = t & 7;
            size_t off = (size_t)r * 512 + kt * 32 + c * 4;
            const uint32_t* H = mat ? Bh : Ah;
            const uint32_t* L = mat ? Bl : Al;
            uint4 hi = *reinterpret_cast<const uint4*>(H + off);
            uint4 lo = *reinterpret_cast<const uint4*>(L + off);
            uint32_t o = ((uint32_t)r << 7) + ((uint32_t)c << 4);
            uint32_t sw = o ^ ((o >> 3) & 0x70);
            char* tb = sm + stg + mat * 32768;
            *reinterpret_cast<uint4*>(tb + sw) = hi;
            *reinterpret_cast<uint4*>(tb + 16384 + sw) = lo;
        }
        asm volatile("fence.proxy.async.shared::cta;" ::: "memory");
        __syncthreads();

        if (wid == 0 && elect1()) {
            uint32_t aH = sbase + stg;
            uint64_t dAH = mk_desc(aH);
            uint64_t dAL = mk_desc(aH + 16384);
            uint64_t dBH = mk_desc(aH + 32768);
            uint64_t dBL = mk_desc(aH + 49152);
#pragma unroll
            for (int kc = 0; kc < 4; ++kc) {
                mma_ss(tmem, dAH + kc * 2, dBH + kc * 2, (kt == 0 && kc == 0) ? 0u : 1u);
                mma_ss(tmem, dAH + kc * 2, dBL + kc * 2, 1u);
                mma_ss(tmem, dAL + kc * 2, dBH + kc * 2, 1u);
            }
            tc_commit(sbase + 16 + slot * 8);
        }
    }

    mbar_wait(sbase + 24, 1);
    asm volatile("tcgen05.fence::after_thread_sync;" ::: "memory");

    if (tid < 128) {
        int row = tid;
        float* Crow = C + (size_t)row * 256;
#pragma unroll
        for (int cb = 0; cb < 128; cb += 32) {
            uint32_t rr[32];
            TC_LD_X32(rr, tmem + cb);
            asm volatile("tcgen05.wait::ld.sync.aligned;" ::: "memory");
#pragma unroll
            for (int c = 0; c < 32; c += 4) {
                float4 o;
                o.x = __uint_as_float(rr[c + 0]);
                o.y = __uint_as_float(rr[c + 1]);
                o.z = __uint_as_float(rr[c + 2]);
                o.w = __uint_as_float(rr[c + 3]);
                *reinterpret_cast<float4*>(Crow + cb + c) = o;
            }
        }
    }
    __syncthreads();
    if (wid == 0) {
        asm volatile("tcgen05.dealloc.cta_group::1.sync.aligned.b32 %0, %1;"
                     :: "r"(tmem), "r"(128u));
    }
#else
    gemm_fb<false, false>(Ah, Al, nullptr, Bh, Bl, nullptr, sm);
    __syncthreads();
    float (*Cs)[128] = reinterpret_cast<float (*)[128]>(sm + 66560);
    for (int idx = tid; idx < 128 * 32; idx += 256) {
        int row = idx >> 5;
        int cg = (idx & 31) * 4;
        *reinterpret_cast<float4*>(C + (size_t)row * 256 + cg) =
            *reinterpret_cast<float4*>(&Cs[row][cg]);
    }
#endif
}

// ---------------- top-k reduction over 64 tiles x 4 cands ----------------
// grid (RR, BB), 64 threads
__global__ void topk_reduce_kernel() {
    __shared__ float sv[256];
    __shared__ int   si[256];
    __shared__ float rv[64];
    __shared__ int   ri[64];
    int r = blockIdx.x, b = blockIdx.y;
    int tid = threadIdx.x;

    float4 v = *reinterpret_cast<const float4*>(&g_cand_val[b][tid][r][0]);
    int4   ii = *reinterpret_cast<const int4*>(&g_cand_idx[b][tid][r][0]);
    sv[tid * 4 + 0] = v.x; si[tid * 4 + 0] = ii.x;
    sv[tid * 4 + 1] = v.y; si[tid * 4 + 1] = ii.y;
    sv[tid * 4 + 2] = v.z; si[tid * 4 + 2] = ii.z;
    sv[tid * 4 + 3] = v.w; si[tid * 4 + 3] = ii.w;
    __syncthreads();

    for (int sel = 0; sel < KTOP; sel++) {
        float m = NEG_INF;
        int mi = 0;
#pragma unroll
        for (int j = tid; j < 256; j += 64) {
            if (sv[j] > m) { m = sv[j]; mi = j; }
        }
        rv[tid] = m; ri[tid] = mi;
        __syncthreads();
        for (int s = 32; s > 0; s >>= 1) {
            if (tid < s && rv[tid + s] > rv[tid]) { rv[tid] = rv[tid + s]; ri[tid] = ri[tid + s]; }
            __syncthreads();
        }
        if (tid == 0) {
            int pos = ri[0];
            g_topk[b][r][sel] = si[pos];
            sv[pos] = NEG_INF;
        }
        __syncthreads();
    }
}

// ---------------- gather H + RH dots ----------------
// grid (4, 128, B), 256 threads
__global__ void gather_h_kernel(const float* __restrict__ teacher) {
    __shared__ float sb[256];
    int k = blockIdx.x, r = blockIdx.y, b = blockIdx.z;
    int idx = g_topk[b][r][k];
    int f = 1 + 2 * (idx >> 11);
    int p = idx & 2047;
    const float* src = teacher + (((size_t)b * 8 + f) * PP + p) * D;
    int row = 256 + r * 4 + k;
    const float* rt = &g_X[b][r][0];
    const float* rs = &g_X[b][128 + r][0];
    int tid = threadIdx.x;
    float4 v  = ld4(src + tid * 4);
    float4 t4 = ld4(rt + tid * 4);
    float4 s4 = ld4(rs + tid * 4);
    uint2 hi, lo;
    cvt2(v.x, v.y, hi.x, lo.x);
    cvt2(v.z, v.w, hi.y, lo.y);
    *reinterpret_cast<uint2*>(&g_Xh[b][row][tid * 2]) = hi;
    *reinterpret_cast<uint2*>(&g_Xl[b][row][tid * 2]) = lo;
    float st = v.x * t4.x + v.y * t4.y + v.z * t4.z + v.w * t4.w;
    float ss = v.x * s4.x + v.y * s4.y + v.z * s4.z + v.w * s4.w;
    st = block_reduce_sum(st, sb, 256);
    ss = block_reduce_sum(ss, sb, 256);
    if (tid == 0) {
        float hn2 = g_en2[b][idx];
        g_RHt[b][r][k] = st;
        g_RHs[b][r][k] = ss;
        g_Hn2[b][r][k] = hn2;
        g_nRHt[b][r][k] = fmaxf(sqrtf(fmaxf(g_rtn2[b][r] + hn2 - 2.f * st, 0.f)), EPSA);
        g_nRHs[b][r][k] = fmaxf(sqrtf(fmaxf(g_rsn2[b][r] + hn2 - 2.f * ss, 0.f)), EPSA);
    }
}

// ---------------- elementwise angle + huber loss ----------------
__device__ __forceinline__ float huber(float e) {
    float ae = fabsf(e);
    return (ae <= 1.0f) ? 0.5f * e * e : (ae - 0.5f);
}

// grid (128, B, 3), 128 threads (thread = s)
__global__ void loss_kernel() {
    __shared__ float sb[128];
    int r = blockIdx.x, b = blockIdx.y, pair = blockIdx.z;
    int s = threadIdx.x;

    float rtn2 = g_rtn2[b][r];
    float rsn2 = g_rsn2[b][r];
    float sht2 = g_shn2[pair][b][0][s];
    float shs2 = g_shn2[pair][b][1][s];
    const float* Tb = &g_T[pair][b][0][0];

    float RSht = Tb[(size_t)r * 256 + s];
    float RShs = Tb[(size_t)(128 + r) * 256 + 128 + s];
    float nRSht = fmaxf(sqrtf(fmaxf(rtn2 + sht2 - 2.f * RSht, 0.f)), EPSA);
    float nRShs = fmaxf(sqrtf(fmaxf(rsn2 + shs2 - 2.f * RShs, 0.f)), EPSA);

    float acc = 0.f;
#pragma unroll
    for (int k = 0; k < KTOP; k++) {
        float RHt = g_RHt[b][r][k];
        float RHs = g_RHs[b][r][k];
        float hn2 = g_Hn2[b][r][k];
        float nRHt = g_nRHt[b][r][k];
        float nRHs = g_nRHs[b][r][k];
        float HSht = Tb[(size_t)(256 + r * 4 + k) * 256 + s];
        float HShs = Tb[(size_t)(256 + r * 4 + k) * 256 + 128 + s];
        float nHSht = fmaxf(sqrtf(fmaxf(hn2 + sht2 - 2.f * HSht, 0.f)), EPSA);
        float nHShs = fmaxf(sqrtf(fmaxf(hn2 + shs2 - 2.f * HShs, 0.f)), EPSA);

        float a1t = (HSht - RSht - RHt + rtn2) / (nRSht * nRHt);
        float a1s = (HShs - RShs - RHs + rsn2) / (nRShs * nRHs);
        acc += huber(a1s - a1t);

        float a2t = (RSht - RHt - HSht + hn2) / (nRHt * nHSht);
        float a2s = (RShs - RHs - HShs + hn2) / (nRHs * nHShs);
        acc += huber(a2s - a2t);

        float a3t = (RHt - RSht - HSht + sht2) / (nRSht * nHSht);
        float a3s = (RHs - RShs - HShs + shs2) / (nRShs * nHShs);
        acc += huber(a3s - a3t);
    }
    acc = block_reduce_sum(acc, sb, 128);
    if (threadIdx.x == 0) {
        g_partial[(pair * BB + b) * RR + r] = acc;
    }
}

__global__ void finalize_kernel(float* __restrict__ out) {
    __shared__ float sb[256];
    int tid = threadIdx.x;
    float v = g_partial[tid] + g_partial[tid + 256] + g_partial[tid + 512];
    v = block_reduce_sum(v, sb, 256);
    if (tid == 0) {
        out[0] = v / (float)(NPAIR * BB * RR * SS * KTOP);
    }
}

// ---------------- launch ----------------
extern "C" void kernel_launch(void* const* d_in, const int* in_sizes, int n_in,
                              void* d_out, int out_size) {
    const float* teacher = (const float*)d_in[0];
    const float* student = (const float*)d_in[1];
    const int* ref_perm = (const int*)d_in[2];
    const int* shared_perm = (const int*)d_in[3];
    float* out = (float*)d_out;

    cudaFuncSetAttribute(sim_tc_kernel, cudaFuncAttributeMaxDynamicSharedMemorySize, SMEM_TC_TOTAL);
    cudaFuncSetAttribute(t_tc_kernel, cudaFuncAttributeMaxDynamicSharedMemorySize, SMEM_TC_TOTAL);

    gather_refs_kernel<<<dim3(RR, BB, 2), 256>>>(teacher, student, ref_perm);
    gather_sh_kernel<<<dim3(SS, BB, 6), 256>>>(teacher, student, shared_perm);
    sim_tc_kernel<<<dim3(NTILE, BB), 256, SMEM_TC_TOTAL>>>(teacher);
    topk_reduce_kernel<<<dim3(RR, BB), 64>>>();
    gather_h_kernel<<<dim3(KTOP, RR, BB), 256>>>(teacher);
    t_tc_kernel<<<dim3(2, 6, 6), 256, SMEM_TC_TOTAL>>>();
    loss_kernel<<<dim3(RR, BB, NPAIR), 128>>>();
    finalize_kernel<<<1, 256>>>(out);
}